// round 6
// baseline (speedup 1.0000x reference)
#include <cuda_runtime.h>
#include <cstdint>
#include <math.h>
#include <mma.h>

using namespace nvcuda;

// Problem constants
#define BB 2
#define SS 2048
#define HH 12
#define DHD 64
#define DD 768
#define DFF 3072
#define MM (BB*SS)
#define Y_ELEMS ((size_t)BB*SS*DD)

// ---------------- scratch (device globals) ---------------------------------
__device__ float g_q [BB*HH*SS*DHD];
__device__ float g_k [BB*HH*SS*DHD];
__device__ float g_v [BB*HH*SS*DHD];
__device__ float g_av[BB*SS*DD];
__device__ float g_ao[BB*SS*DD];
__device__ float g_h [BB*SS*DD];
__device__ float g_f1[BB*SS*DFF];
__device__ float g_f2[BB*SS*DD];

__device__ __forceinline__ float4 cvt_tf32_4(float4 v) {
    v.x = wmma::__float_to_tf32(v.x);
    v.y = wmma::__float_to_tf32(v.y);
    v.z = wmma::__float_to_tf32(v.z);
    v.w = wmma::__float_to_tf32(v.w);
    return v;
}

__device__ __forceinline__ void cp_async16(unsigned int dst, const void* src) {
    asm volatile("cp.async.cg.shared.global [%0], [%1], 16;\n" :: "r"(dst), "l"(src));
}
__device__ __forceinline__ void cp_commit() {
    asm volatile("cp.async.commit_group;\n");
}
__device__ __forceinline__ void cp_wait0() {
    asm volatile("cp.async.wait_group 0;\n");
}

// ============  tf32 NT GEMM, double-buffered, 2 CTAs/SM  ===================
#define GLD 36
#define GBUF (128*GLD)
#define GEMM_SMEM_BYTES (4*GBUF*4)

// shared GEMM body: C[m,n] = sum_k A[m,k]*B[n,k]
template<int MODE>
__device__ __forceinline__ void gemm_body(const float* __restrict__ A,
                                          const float* __restrict__ B,
                                          float* __restrict__ C,
                                          int N, int K, int m0, int n0)
{
    extern __shared__ float gsm[];
    float* As = gsm;
    float* Bs = gsm + 2*GBUF;

    const int tid  = threadIdx.x;
    const int warp = tid >> 5;
    const int wm   = warp & 1;
    const int wn   = warp >> 1;
    const int lr   = tid >> 3;
    const int lc4  = (tid & 7) * 4;

    wmma::fragment<wmma::accumulator, 16, 16, 8, float> c[4][2];
    #pragma unroll
    for (int i = 0; i < 4; i++)
        #pragma unroll
        for (int j = 0; j < 2; j++)
            wmma::fill_fragment(c[i][j], 0.0f);

    const int T = K >> 5;
    float4 pa[4], pb[4];

    #pragma unroll
    for (int i = 0; i < 4; i++) {
        int row = lr + i * 32;
        pa[i] = *(const float4*)&A[(size_t)(m0 + row) * K + lc4];
        pb[i] = *(const float4*)&B[(size_t)(n0 + row) * K + lc4];
    }
    #pragma unroll
    for (int i = 0; i < 4; i++) {
        int row = lr + i * 32;
        *(float4*)&As[row * GLD + lc4] = cvt_tf32_4(pa[i]);
        *(float4*)&Bs[row * GLD + lc4] = cvt_tf32_4(pb[i]);
    }
    __syncthreads();

    for (int t = 0; t < T; t++) {
        const int cur = (t & 1) * GBUF;
        const bool pf = (t + 1 < T);
        if (pf) {
            const int k0 = (t + 1) << 5;
            #pragma unroll
            for (int i = 0; i < 4; i++) {
                int row = lr + i * 32;
                pa[i] = *(const float4*)&A[(size_t)(m0 + row) * K + k0 + lc4];
                pb[i] = *(const float4*)&B[(size_t)(n0 + row) * K + k0 + lc4];
            }
        }

        #pragma unroll
        for (int kk = 0; kk < 32; kk += 8) {
            wmma::fragment<wmma::matrix_a, 16, 16, 8, wmma::precision::tf32, wmma::row_major> a[4];
            wmma::fragment<wmma::matrix_b, 16, 16, 8, wmma::precision::tf32, wmma::col_major> b[2];
            #pragma unroll
            for (int i = 0; i < 4; i++)
                wmma::load_matrix_sync(a[i], &As[cur + (wm * 64 + i * 16) * GLD + kk], GLD);
            #pragma unroll
            for (int j = 0; j < 2; j++)
                wmma::load_matrix_sync(b[j], &Bs[cur + (wn * 32 + j * 16) * GLD + kk], GLD);
            #pragma unroll
            for (int i = 0; i < 4; i++)
                #pragma unroll
                for (int j = 0; j < 2; j++)
                    wmma::mma_sync(c[i][j], a[i], b[j], c[i][j]);
        }

        if (pf) {
            const int nxt = ((t + 1) & 1) * GBUF;
            #pragma unroll
            for (int i = 0; i < 4; i++) {
                int row = lr + i * 32;
                *(float4*)&As[nxt + row * GLD + lc4] = cvt_tf32_4(pa[i]);
                *(float4*)&Bs[nxt + row * GLD + lc4] = cvt_tf32_4(pb[i]);
            }
        }
        __syncthreads();
    }

    #pragma unroll
    for (int i = 0; i < 4; i++) {
        int m = m0 + wm * 64 + i * 16;
        #pragma unroll
        for (int j = 0; j < 2; j++) {
            int n = n0 + wn * 32 + j * 16;
            if (MODE == 3) {
                int bidx = m >> 11, s = m & 2047;
                int h = n >> 6, dh = n & 63;
                float* dst = C + (((size_t)(bidx * HH + h)) * SS + s) * DHD + dh;
                wmma::store_matrix_sync(dst, c[i][j], DHD, wmma::mem_row_major);
            } else {
                wmma::store_matrix_sync(C + (size_t)m * N + n, c[i][j], N, wmma::mem_row_major);
            }
        }
    }
}

__global__ void __launch_bounds__(256, 2)
gemm_tc_nt(const float* __restrict__ A, const float* __restrict__ B,
           float* __restrict__ C, int N, int K)
{
    gemm_body<0>(A, B, C, N, K, blockIdx.y * 128, blockIdx.x * 128);
}

// merged QKV: grid.z selects (W, out) pair; head-split store
__global__ void __launch_bounds__(256, 2)
qkv_gemm(const float* __restrict__ X,
         const float* __restrict__ Wq, const float* __restrict__ Wk,
         const float* __restrict__ Wv,
         float* __restrict__ Qo, float* __restrict__ Ko, float* __restrict__ Vo)
{
    const float* B = (blockIdx.z == 0) ? Wq : (blockIdx.z == 1) ? Wk : Wv;
    float*       C = (blockIdx.z == 0) ? Qo : (blockIdx.z == 1) ? Ko : Vo;
    gemm_body<3>(X, B, C, DD, DD, blockIdx.y * 128, blockIdx.x * 128);
}

// ==============  fused flash attention, cp.async pipelined  ================
#define ATT_LDQ 68
#define QBUF (128*ATT_LDQ)
#define ATT_LDS 132
#define ATT_SMEM_FLOATS (4*QBUF + 128*ATT_LDS + 128)   // Q,K,V[2],S,ls

__global__ void __launch_bounds__(512, 1)
attn_fused(const float* __restrict__ Q, const float* __restrict__ K,
           const float* __restrict__ V, float* __restrict__ P,
           float* __restrict__ AV)
{
    extern __shared__ float sm[];
    float* Qs = sm;                 // [128][68] tf32
    float* Ks = Qs + QBUF;          // [128][68]
    float* Vs = Ks + QBUF;          // [2][128][68]
    float* Ss = Vs + 2*QBUF;        // [128][132]
    float* ls = Ss + 128 * ATT_LDS; // [128]

    const int bh  = blockIdx.y;
    const int qt  = gridDim.x - 1 - blockIdx.x;
    const int m0  = qt * 128;
    const int tid = threadIdx.x;
    const int warp = tid >> 5;
    const int wm = warp & 3;
    const int wn = warp >> 2;

    const float* Qb = Q + ((size_t)bh * SS + m0) * DHD;
    const float* Kb = K + (size_t)bh * SS * DHD;
    const float* Vb = V + (size_t)bh * SS * DHD;
    float* Pb = P + ((size_t)bh * SS + m0) * SS;

    // per-thread cp.async slots: 4 x 16B per matrix tile
    const int pr  = tid >> 4;          // 0..31 (+u*32)
    const int pc4 = (tid & 15) * 4;
    const unsigned int ks_s = (unsigned int)__cvta_generic_to_shared(Ks);
    const unsigned int vs_s = (unsigned int)__cvta_generic_to_shared(Vs);

    // load Q tile (scaled by 1/8, tf32)
    for (int i = tid; i < 128 * 16; i += 512) {
        int r = i >> 4, c4 = (i & 15) * 4;
        float4 v = *(const float4*)&Qb[(size_t)r * DHD + c4];
        v.x *= 0.125f; v.y *= 0.125f; v.z *= 0.125f; v.w *= 0.125f;
        *(float4*)&Qs[r * ATT_LDQ + c4] = cvt_tf32_4(v);
    }
    if (tid < 128) ls[tid] = 0.0f;

    // issue copies for kt = 0
    #pragma unroll
    for (int u = 0; u < 4; u++) {
        int r = pr + u * 32;
        cp_async16(ks_s + (r * ATT_LDQ + pc4) * 4, &Kb[(size_t)r * DHD + pc4]);
        cp_async16(vs_s + (r * ATT_LDQ + pc4) * 4, &Vb[(size_t)r * DHD + pc4]);
    }
    cp_commit();

    wmma::fragment<wmma::accumulator, 16, 16, 8, float> co[2];
    #pragma unroll
    for (int i = 0; i < 2; i++) wmma::fill_fragment(co[i], 0.0f);

    for (int kt = 0; kt <= qt; kt++) {
        const int cur = (kt & 1) * QBUF;
        cp_wait0();
        // convert own copied bytes to tf32 (self-owned; no sync needed first)
        #pragma unroll
        for (int u = 0; u < 4; u++) {
            int off = (pr + u * 32) * ATT_LDQ + pc4;
            *(float4*)&Ks[off]       = cvt_tf32_4(*(float4*)&Ks[off]);
            *(float4*)&Vs[cur + off] = cvt_tf32_4(*(float4*)&Vs[cur + off]);
        }
        __syncthreads();

        // S = Qs @ Ks^T  (warp tile 32x32)
        wmma::fragment<wmma::accumulator, 16, 16, 8, float> cs[2][2];
        #pragma unroll
        for (int i = 0; i < 2; i++)
            #pragma unroll
            for (int j = 0; j < 2; j++)
                wmma::fill_fragment(cs[i][j], 0.0f);

        #pragma unroll
        for (int kk = 0; kk < 64; kk += 8) {
            wmma::fragment<wmma::matrix_a, 16, 16, 8, wmma::precision::tf32, wmma::row_major> a[2];
            wmma::fragment<wmma::matrix_b, 16, 16, 8, wmma::precision::tf32, wmma::col_major> b[2];
            #pragma unroll
            for (int i = 0; i < 2; i++)
                wmma::load_matrix_sync(a[i], &Qs[(wm * 32 + i * 16) * ATT_LDQ + kk], ATT_LDQ);
            #pragma unroll
            for (int j = 0; j < 2; j++)
                wmma::load_matrix_sync(b[j], &Ks[(wn * 32 + j * 16) * ATT_LDQ + kk], ATT_LDQ);
            #pragma unroll
            for (int i = 0; i < 2; i++)
                #pragma unroll
                for (int j = 0; j < 2; j++)
                    wmma::mma_sync(cs[i][j], a[i], b[j], cs[i][j]);
        }
        #pragma unroll
        for (int i = 0; i < 2; i++)
            #pragma unroll
            for (int j = 0; j < 2; j++)
                wmma::store_matrix_sync(&Ss[(wm * 32 + i * 16) * ATT_LDS + wn * 32 + j * 16],
                                        cs[i][j], ATT_LDS, wmma::mem_row_major);
        __syncthreads();   // Ss visible; all warps done reading Ks

        // prefetch tiles for kt+1 (overlaps exp + O-MMA)
        if (kt < qt) {
            const int k1 = (kt + 1) * 128;
            const unsigned int vdst = vs_s + (((kt + 1) & 1) * QBUF) * 4;
            #pragma unroll
            for (int u = 0; u < 4; u++) {
                int r = pr + u * 32;
                cp_async16(ks_s + (r * ATT_LDQ + pc4) * 4, &Kb[(size_t)(k1 + r) * DHD + pc4]);
                cp_async16(vdst + (r * ATT_LDQ + pc4) * 4, &Vb[(size_t)(k1 + r) * DHD + pc4]);
            }
            cp_commit();
        }

        // exp + causal mask + rowsum; fp32 e -> P, tf32 e -> Ss
        {
            const int k0 = kt * 128;
            int r  = tid >> 2;
            int c0 = (tid & 3) * 32;
            int grow = m0 + r;
            float partial = 0.0f;
            #pragma unroll
            for (int c = 0; c < 32; c += 4) {
                int gc = k0 + c0 + c;
                float4 v = *(float4*)&Ss[r * ATT_LDS + c0 + c];
                v.x = (gc + 0 <= grow) ? __expf(v.x) : 0.0f;
                v.y = (gc + 1 <= grow) ? __expf(v.y) : 0.0f;
                v.z = (gc + 2 <= grow) ? __expf(v.z) : 0.0f;
                v.w = (gc + 3 <= grow) ? __expf(v.w) : 0.0f;
                partial += v.x + v.y + v.z + v.w;
                *(float4*)&Pb[(size_t)r * SS + gc] = v;
                *(float4*)&Ss[r * ATT_LDS + c0 + c] = cvt_tf32_4(v);
            }
            atomicAdd(&ls[r], partial);
        }
        __syncthreads();

        // O += e @ V  (warp tile 32x16)
        #pragma unroll
        for (int kk = 0; kk < 128; kk += 8) {
            wmma::fragment<wmma::matrix_a, 16, 16, 8, wmma::precision::tf32, wmma::row_major> a[2];
            wmma::fragment<wmma::matrix_b, 16, 16, 8, wmma::precision::tf32, wmma::row_major> b;
            #pragma unroll
            for (int i = 0; i < 2; i++)
                wmma::load_matrix_sync(a[i], &Ss[(wm * 32 + i * 16) * ATT_LDS + kk], ATT_LDS);
            wmma::load_matrix_sync(b, &Vs[cur + kk * ATT_LDQ + wn * 16], ATT_LDQ);
            #pragma unroll
            for (int i = 0; i < 2; i++)
                wmma::mma_sync(co[i], a[i], b, co[i]);
        }
        __syncthreads();
    }

    // zero-fill fully masked P region
    const int zc0 = (qt + 1) * 128;
    if (zc0 < SS) {
        const int rl4 = (SS - zc0) >> 2;
        const float4 z4 = make_float4(0.f, 0.f, 0.f, 0.f);
        for (int i = tid; i < 128 * rl4; i += 512) {
            int r = i / rl4, c4 = (i - r * rl4) * 4;
            *(float4*)&Pb[(size_t)r * SS + zc0 + c4] = z4;
        }
    }

    // stage O to smem, normalize, write AV
    #pragma unroll
    for (int i = 0; i < 2; i++)
        wmma::store_matrix_sync(&Ss[(wm * 32 + i * 16) * ATT_LDQ + wn * 16],
                                co[i], ATT_LDQ, wmma::mem_row_major);
    __syncthreads();

    const int bi = bh / HH, hi = bh % HH;
    {
        int r  = tid >> 2;
        int c0 = (tid & 3) * 16;
        float inv = 1.0f / ls[r];
        float* dst = AV + ((size_t)bi * SS + m0 + r) * DD + hi * DHD + c0;
        #pragma unroll
        for (int c = 0; c < 16; c += 4) {
            float4 v = *(float4*)&Ss[r * ATT_LDQ + c0 + c];
            v.x *= inv; v.y *= inv; v.z *= inv; v.w *= inv;
            *(float4*)&dst[c] = v;
        }
    }

    // rescale lower-triangle P by 1/rowsum
    {
        const int rl4 = zc0 >> 2;
        for (int i = tid; i < 128 * rl4; i += 512) {
            int r = i / rl4, c4 = (i - r * rl4) * 4;
            float inv = 1.0f / ls[r];
            float4 v = *(float4*)&Pb[(size_t)r * SS + c4];
            v.x *= inv; v.y *= inv; v.z *= inv; v.w *= inv;
            *(float4*)&Pb[(size_t)r * SS + c4] = v;
        }
    }
}

// ---------------- bias + exact GELU ----------------------------------------
__global__ void bias_gelu(float* __restrict__ F, const float* __restrict__ bias)
{
    const int idx4 = blockIdx.x * 256 + threadIdx.x;
    const size_t base = (size_t)idx4 * 4;
    float4 v = *(float4*)&F[base];
    const int col = (int)(base % DFF);
    float4 bb = *(const float4*)&bias[col];
    v.x += bb.x; v.y += bb.y; v.z += bb.z; v.w += bb.w;
    v.x = 0.5f * v.x * (1.0f + erff(v.x * 0.70710678118654752f));
    v.y = 0.5f * v.y * (1.0f + erff(v.y * 0.70710678118654752f));
    v.z = 0.5f * v.z * (1.0f + erff(v.z * 0.70710678118654752f));
    v.w = 0.5f * v.w * (1.0f + erff(v.w * 0.70710678118654752f));
    *(float4*)&F[base] = v;
}

// ---------------- fused residual add (+bias) + LayerNorm ------------------
__global__ void add_ln(const float* __restrict__ A, const float* __restrict__ Bv,
                       const float* __restrict__ bias,
                       const float* __restrict__ gamma, const float* __restrict__ beta,
                       float* __restrict__ out)
{
    const int row = blockIdx.x;
    const int tid = threadIdx.x;
    __shared__ float buf[DD];
    __shared__ float red[8];

    const float* a  = A  + (size_t)row * DD;
    const float* bp = Bv + (size_t)row * DD;

    float lsum = 0.f;
    #pragma unroll
    for (int i = 0; i < 3; i++) {
        int c = tid + i * 256;
        float v = a[c] + bp[c] + (bias ? bias[c] : 0.0f);
        buf[c] = v;
        lsum += v;
    }
    #pragma unroll
    for (int o = 16; o; o >>= 1) lsum += __shfl_xor_sync(0xffffffffu, lsum, o);
    if ((tid & 31) == 0) red[tid >> 5] = lsum;
    __syncthreads();
    float mu = (red[0]+red[1]+red[2]+red[3]+red[4]+red[5]+red[6]+red[7]) * (1.0f / DD);

    float lvar = 0.f;
    #pragma unroll
    for (int i = 0; i < 3; i++) {
        int c = tid + i * 256;
        float d = buf[c] - mu;
        lvar += d * d;
    }
    #pragma unroll
    for (int o = 16; o; o >>= 1) lvar += __shfl_xor_sync(0xffffffffu, lvar, o);
    __syncthreads();
    if ((tid & 31) == 0) red[tid >> 5] = lvar;
    __syncthreads();
    float var = (red[0]+red[1]+red[2]+red[3]+red[4]+red[5]+red[6]+red[7]) * (1.0f / DD);
    float inv = rsqrtf(var + 1e-5f);

    float* o = out + (size_t)row * DD;
    #pragma unroll
    for (int i = 0; i < 3; i++) {
        int c = tid + i * 256;
        o[c] = (buf[c] - mu) * inv * gamma[c] + beta[c];
    }
}

// ---------------------------------------------------------------------------
extern "C" void kernel_launch(void* const* d_in, const int* in_sizes, int n_in,
                              void* d_out, int out_size)
{
    const float* x   = (const float*)d_in[0];
    const float* Wq  = (const float*)d_in[2];
    const float* Wk  = (const float*)d_in[3];
    const float* Wv  = (const float*)d_in[4];
    const float* Wo  = (const float*)d_in[5];
    const float* bo  = (const float*)d_in[6];
    const float* g1  = (const float*)d_in[7];
    const float* b1  = (const float*)d_in[8];
    const float* W1  = (const float*)d_in[9];
    const float* bb1 = (const float*)d_in[10];
    const float* W2  = (const float*)d_in[11];
    const float* bb2 = (const float*)d_in[12];
    const float* g2  = (const float*)d_in[13];
    const float* b2  = (const float*)d_in[14];

    float* y = (float*)d_out;
    float* P = y + Y_ELEMS;

    float *qp, *kp, *vp, *avp, *aop, *hp, *f1p, *f2p;
    cudaGetSymbolAddress((void**)&qp,  g_q);
    cudaGetSymbolAddress((void**)&kp,  g_k);
    cudaGetSymbolAddress((void**)&vp,  g_v);
    cudaGetSymbolAddress((void**)&avp, g_av);
    cudaGetSymbolAddress((void**)&aop, g_ao);
    cudaGetSymbolAddress((void**)&hp,  g_h);
    cudaGetSymbolAddress((void**)&f1p, g_f1);
    cudaGetSymbolAddress((void**)&f2p, g_f2);

    cudaFuncSetAttribute(gemm_tc_nt, cudaFuncAttributeMaxDynamicSharedMemorySize,
                         GEMM_SMEM_BYTES);
    cudaFuncSetAttribute(qkv_gemm, cudaFuncAttributeMaxDynamicSharedMemorySize,
                         GEMM_SMEM_BYTES);
    static const size_t att_smem = (size_t)ATT_SMEM_FLOATS * sizeof(float);
    cudaFuncSetAttribute(attn_fused, cudaFuncAttributeMaxDynamicSharedMemorySize,
                         (int)att_smem);

    dim3 g768 (DD  / 128, MM / 128);
    dim3 g3072(DFF / 128, MM / 128);
    dim3 gqkv (DD  / 128, MM / 128, 3);

    // QKV projections: single merged launch, head-split outputs
    qkv_gemm<<<gqkv, 256, GEMM_SMEM_BYTES>>>(x, Wq, Wk, Wv, qp, kp, vp);

    // fused attention (cp.async pipelined)
    attn_fused<<<dim3(SS / 128, BB * HH), 512, att_smem>>>(qp, kp, vp, P, avp);

    // output projection (bias folded into add_ln)
    gemm_tc_nt<<<g768, 256, GEMM_SMEM_BYTES>>>(avp, Wo, aop, DD, DD);

    add_ln<<<MM, 256>>>(x, aop, bo, g1, b1, hp);

    gemm_tc_nt<<<g3072, 256, GEMM_SMEM_BYTES>>>(hp, W1, f1p, DFF, DD);
    bias_gelu<<<(int)((size_t)MM * DFF / 4 / 256), 256>>>(f1p, bb1);
    gemm_tc_nt<<<g768, 256, GEMM_SMEM_BYTES>>>(f1p, W2, f2p, DD, DFF);

    add_ln<<<MM, 256>>>(hp, f2p, bb2, g2, b2, y);
}

// round 7
// speedup vs baseline: 1.4913x; 1.4913x over previous
#include <cuda_runtime.h>
#include <cstdint>
#include <math.h>
#include <mma.h>

using namespace nvcuda;

// Problem constants
#define BB 2
#define SS 2048
#define HH 12
#define DHD 64
#define DD 768
#define DFF 3072
#define MM (BB*SS)
#define Y_ELEMS ((size_t)BB*SS*DD)

// ---------------- scratch (device globals) ---------------------------------
__device__ float g_q [BB*HH*SS*DHD];
__device__ float g_k [BB*HH*SS*DHD];
__device__ float g_v [BB*HH*SS*DHD];
__device__ float g_av[BB*SS*DD];
__device__ float g_ao[BB*SS*DD];
__device__ float g_h [BB*SS*DD];
__device__ float g_f1[BB*SS*DFF];
__device__ float g_f2[BB*SS*DD];

__device__ __forceinline__ float4 cvt_tf32_4(float4 v) {
    v.x = wmma::__float_to_tf32(v.x);
    v.y = wmma::__float_to_tf32(v.y);
    v.z = wmma::__float_to_tf32(v.z);
    v.w = wmma::__float_to_tf32(v.w);
    return v;
}

__device__ __forceinline__ void cp_async16(unsigned int dst, const void* src) {
    asm volatile("cp.async.cg.shared.global [%0], [%1], 16;\n" :: "r"(dst), "l"(src));
}
__device__ __forceinline__ void cp_commit() {
    asm volatile("cp.async.commit_group;\n");
}
__device__ __forceinline__ void cp_wait0() {
    asm volatile("cp.async.wait_group 0;\n");
}

// ============  tf32 NT GEMM, double-buffered (NO reg cap)  =================
#define GLD 36
#define GBUF (128*GLD)
#define GEMM_SMEM_BYTES (4*GBUF*4)

// shared GEMM body: C[m,n] = sum_k A[m,k]*B[n,k]
template<int MODE>
__device__ __forceinline__ void gemm_body(const float* __restrict__ A,
                                          const float* __restrict__ B,
                                          float* __restrict__ C,
                                          int N, int K, int m0, int n0)
{
    extern __shared__ float gsm[];
    float* As = gsm;
    float* Bs = gsm + 2*GBUF;

    const int tid  = threadIdx.x;
    const int warp = tid >> 5;
    const int wm   = warp & 1;
    const int wn   = warp >> 1;
    const int lr   = tid >> 3;
    const int lc4  = (tid & 7) * 4;

    wmma::fragment<wmma::accumulator, 16, 16, 8, float> c[4][2];
    #pragma unroll
    for (int i = 0; i < 4; i++)
        #pragma unroll
        for (int j = 0; j < 2; j++)
            wmma::fill_fragment(c[i][j], 0.0f);

    const int T = K >> 5;
    float4 pa[4], pb[4];

    #pragma unroll
    for (int i = 0; i < 4; i++) {
        int row = lr + i * 32;
        pa[i] = *(const float4*)&A[(size_t)(m0 + row) * K + lc4];
        pb[i] = *(const float4*)&B[(size_t)(n0 + row) * K + lc4];
    }
    #pragma unroll
    for (int i = 0; i < 4; i++) {
        int row = lr + i * 32;
        *(float4*)&As[row * GLD + lc4] = cvt_tf32_4(pa[i]);
        *(float4*)&Bs[row * GLD + lc4] = cvt_tf32_4(pb[i]);
    }
    __syncthreads();

    for (int t = 0; t < T; t++) {
        const int cur = (t & 1) * GBUF;
        const bool pf = (t + 1 < T);
        if (pf) {
            const int k0 = (t + 1) << 5;
            #pragma unroll
            for (int i = 0; i < 4; i++) {
                int row = lr + i * 32;
                pa[i] = *(const float4*)&A[(size_t)(m0 + row) * K + k0 + lc4];
                pb[i] = *(const float4*)&B[(size_t)(n0 + row) * K + k0 + lc4];
            }
        }

        #pragma unroll
        for (int kk = 0; kk < 32; kk += 8) {
            wmma::fragment<wmma::matrix_a, 16, 16, 8, wmma::precision::tf32, wmma::row_major> a[4];
            wmma::fragment<wmma::matrix_b, 16, 16, 8, wmma::precision::tf32, wmma::col_major> b[2];
            #pragma unroll
            for (int i = 0; i < 4; i++)
                wmma::load_matrix_sync(a[i], &As[cur + (wm * 64 + i * 16) * GLD + kk], GLD);
            #pragma unroll
            for (int j = 0; j < 2; j++)
                wmma::load_matrix_sync(b[j], &Bs[cur + (wn * 32 + j * 16) * GLD + kk], GLD);
            #pragma unroll
            for (int i = 0; i < 4; i++)
                #pragma unroll
                for (int j = 0; j < 2; j++)
                    wmma::mma_sync(c[i][j], a[i], b[j], c[i][j]);
        }

        if (pf) {
            const int nxt = ((t + 1) & 1) * GBUF;
            #pragma unroll
            for (int i = 0; i < 4; i++) {
                int row = lr + i * 32;
                *(float4*)&As[nxt + row * GLD + lc4] = cvt_tf32_4(pa[i]);
                *(float4*)&Bs[nxt + row * GLD + lc4] = cvt_tf32_4(pb[i]);
            }
        }
        __syncthreads();
    }

    #pragma unroll
    for (int i = 0; i < 4; i++) {
        int m = m0 + wm * 64 + i * 16;
        #pragma unroll
        for (int j = 0; j < 2; j++) {
            int n = n0 + wn * 32 + j * 16;
            if (MODE == 3) {
                int bidx = m >> 11, s = m & 2047;
                int h = n >> 6, dh = n & 63;
                float* dst = C + (((size_t)(bidx * HH + h)) * SS + s) * DHD + dh;
                wmma::store_matrix_sync(dst, c[i][j], DHD, wmma::mem_row_major);
            } else {
                wmma::store_matrix_sync(C + (size_t)m * N + n, c[i][j], N, wmma::mem_row_major);
            }
        }
    }
}

__global__ void __launch_bounds__(256)
gemm_tc_nt(const float* __restrict__ A, const float* __restrict__ B,
           float* __restrict__ C, int N, int K)
{
    gemm_body<0>(A, B, C, N, K, blockIdx.y * 128, blockIdx.x * 128);
}

// merged QKV: grid.z selects (W, out) pair; head-split store
__global__ void __launch_bounds__(256)
qkv_gemm(const float* __restrict__ X,
         const float* __restrict__ Wq, const float* __restrict__ Wk,
         const float* __restrict__ Wv,
         float* __restrict__ Qo, float* __restrict__ Ko, float* __restrict__ Vo)
{
    const float* B = (blockIdx.z == 0) ? Wq : (blockIdx.z == 1) ? Wk : Wv;
    float*       C = (blockIdx.z == 0) ? Qo : (blockIdx.z == 1) ? Ko : Vo;
    gemm_body<3>(X, B, C, DD, DD, blockIdx.y * 128, blockIdx.x * 128);
}

// ==============  fused flash attention, cp.async pipelined  ================
#define ATT_LDQ 68
#define QBUF (128*ATT_LDQ)
#define ATT_LDS 132
#define ATT_SMEM_FLOATS (4*QBUF + 128*ATT_LDS + 128)   // Q,K,V[2],S,ls

__global__ void __launch_bounds__(512, 1)
attn_fused(const float* __restrict__ Q, const float* __restrict__ K,
           const float* __restrict__ V, float* __restrict__ P,
           float* __restrict__ AV)
{
    extern __shared__ float sm[];
    float* Qs = sm;                 // [128][68] tf32
    float* Ks = Qs + QBUF;          // [128][68]
    float* Vs = Ks + QBUF;          // [2][128][68]
    float* Ss = Vs + 2*QBUF;        // [128][132]
    float* ls = Ss + 128 * ATT_LDS; // [128]

    const int bh  = blockIdx.y;
    const int qt  = gridDim.x - 1 - blockIdx.x;
    const int m0  = qt * 128;
    const int tid = threadIdx.x;
    const int warp = tid >> 5;
    const int wm = warp & 3;
    const int wn = warp >> 2;

    const float* Qb = Q + ((size_t)bh * SS + m0) * DHD;
    const float* Kb = K + (size_t)bh * SS * DHD;
    const float* Vb = V + (size_t)bh * SS * DHD;
    float* Pb = P + ((size_t)bh * SS + m0) * SS;

    const int pr  = tid >> 4;
    const int pc4 = (tid & 15) * 4;
    const unsigned int ks_s = (unsigned int)__cvta_generic_to_shared(Ks);
    const unsigned int vs_s = (unsigned int)__cvta_generic_to_shared(Vs);

    // load Q tile (scaled by 1/8, tf32)
    for (int i = tid; i < 128 * 16; i += 512) {
        int r = i >> 4, c4 = (i & 15) * 4;
        float4 v = *(const float4*)&Qb[(size_t)r * DHD + c4];
        v.x *= 0.125f; v.y *= 0.125f; v.z *= 0.125f; v.w *= 0.125f;
        *(float4*)&Qs[r * ATT_LDQ + c4] = cvt_tf32_4(v);
    }
    if (tid < 128) ls[tid] = 0.0f;

    // issue copies for kt = 0
    #pragma unroll
    for (int u = 0; u < 4; u++) {
        int r = pr + u * 32;
        cp_async16(ks_s + (r * ATT_LDQ + pc4) * 4, &Kb[(size_t)r * DHD + pc4]);
        cp_async16(vs_s + (r * ATT_LDQ + pc4) * 4, &Vb[(size_t)r * DHD + pc4]);
    }
    cp_commit();

    wmma::fragment<wmma::accumulator, 16, 16, 8, float> co[2];
    #pragma unroll
    for (int i = 0; i < 2; i++) wmma::fill_fragment(co[i], 0.0f);

    for (int kt = 0; kt <= qt; kt++) {
        const int cur = (kt & 1) * QBUF;
        cp_wait0();
        #pragma unroll
        for (int u = 0; u < 4; u++) {
            int off = (pr + u * 32) * ATT_LDQ + pc4;
            *(float4*)&Ks[off]       = cvt_tf32_4(*(float4*)&Ks[off]);
            *(float4*)&Vs[cur + off] = cvt_tf32_4(*(float4*)&Vs[cur + off]);
        }
        __syncthreads();

        // S = Qs @ Ks^T  (warp tile 32x32)
        wmma::fragment<wmma::accumulator, 16, 16, 8, float> cs[2][2];
        #pragma unroll
        for (int i = 0; i < 2; i++)
            #pragma unroll
            for (int j = 0; j < 2; j++)
                wmma::fill_fragment(cs[i][j], 0.0f);

        #pragma unroll
        for (int kk = 0; kk < 64; kk += 8) {
            wmma::fragment<wmma::matrix_a, 16, 16, 8, wmma::precision::tf32, wmma::row_major> a[2];
            wmma::fragment<wmma::matrix_b, 16, 16, 8, wmma::precision::tf32, wmma::col_major> b[2];
            #pragma unroll
            for (int i = 0; i < 2; i++)
                wmma::load_matrix_sync(a[i], &Qs[(wm * 32 + i * 16) * ATT_LDQ + kk], ATT_LDQ);
            #pragma unroll
            for (int j = 0; j < 2; j++)
                wmma::load_matrix_sync(b[j], &Ks[(wn * 32 + j * 16) * ATT_LDQ + kk], ATT_LDQ);
            #pragma unroll
            for (int i = 0; i < 2; i++)
                #pragma unroll
                for (int j = 0; j < 2; j++)
                    wmma::mma_sync(cs[i][j], a[i], b[j], cs[i][j]);
        }
        #pragma unroll
        for (int i = 0; i < 2; i++)
            #pragma unroll
            for (int j = 0; j < 2; j++)
                wmma::store_matrix_sync(&Ss[(wm * 32 + i * 16) * ATT_LDS + wn * 32 + j * 16],
                                        cs[i][j], ATT_LDS, wmma::mem_row_major);
        __syncthreads();   // Ss visible; all warps done reading Ks

        // prefetch tiles for kt+1 (overlaps exp + O-MMA)
        if (kt < qt) {
            const int k1 = (kt + 1) * 128;
            const unsigned int vdst = vs_s + (((kt + 1) & 1) * QBUF) * 4;
            #pragma unroll
            for (int u = 0; u < 4; u++) {
                int r = pr + u * 32;
                cp_async16(ks_s + (r * ATT_LDQ + pc4) * 4, &Kb[(size_t)(k1 + r) * DHD + pc4]);
                cp_async16(vdst + (r * ATT_LDQ + pc4) * 4, &Vb[(size_t)(k1 + r) * DHD + pc4]);
            }
            cp_commit();
        }

        // exp + causal mask + rowsum; fp32 e -> P, tf32 e -> Ss
        {
            const int k0 = kt * 128;
            int r  = tid >> 2;
            int c0 = (tid & 3) * 32;
            int grow = m0 + r;
            float partial = 0.0f;
            #pragma unroll
            for (int c = 0; c < 32; c += 4) {
                int gc = k0 + c0 + c;
                float4 v = *(float4*)&Ss[r * ATT_LDS + c0 + c];
                v.x = (gc + 0 <= grow) ? __expf(v.x) : 0.0f;
                v.y = (gc + 1 <= grow) ? __expf(v.y) : 0.0f;
                v.z = (gc + 2 <= grow) ? __expf(v.z) : 0.0f;
                v.w = (gc + 3 <= grow) ? __expf(v.w) : 0.0f;
                partial += v.x + v.y + v.z + v.w;
                *(float4*)&Pb[(size_t)r * SS + gc] = v;
                *(float4*)&Ss[r * ATT_LDS + c0 + c] = cvt_tf32_4(v);
            }
            atomicAdd(&ls[r], partial);
        }
        __syncthreads();

        // O += e @ V  (warp tile 32x16)
        #pragma unroll
        for (int kk = 0; kk < 128; kk += 8) {
            wmma::fragment<wmma::matrix_a, 16, 16, 8, wmma::precision::tf32, wmma::row_major> a[2];
            wmma::fragment<wmma::matrix_b, 16, 16, 8, wmma::precision::tf32, wmma::row_major> b;
            #pragma unroll
            for (int i = 0; i < 2; i++)
                wmma::load_matrix_sync(a[i], &Ss[(wm * 32 + i * 16) * ATT_LDS + kk], ATT_LDS);
            wmma::load_matrix_sync(b, &Vs[cur + kk * ATT_LDQ + wn * 16], ATT_LDQ);
            #pragma unroll
            for (int i = 0; i < 2; i++)
                wmma::mma_sync(co[i], a[i], b, co[i]);
        }
        __syncthreads();
    }

    // zero-fill fully masked P region
    const int zc0 = (qt + 1) * 128;
    if (zc0 < SS) {
        const int rl4 = (SS - zc0) >> 2;
        const float4 z4 = make_float4(0.f, 0.f, 0.f, 0.f);
        for (int i = tid; i < 128 * rl4; i += 512) {
            int r = i / rl4, c4 = (i - r * rl4) * 4;
            *(float4*)&Pb[(size_t)r * SS + zc0 + c4] = z4;
        }
    }

    // stage O to smem, normalize, write AV
    #pragma unroll
    for (int i = 0; i < 2; i++)
        wmma::store_matrix_sync(&Ss[(wm * 32 + i * 16) * ATT_LDQ + wn * 16],
                                co[i], ATT_LDQ, wmma::mem_row_major);
    __syncthreads();

    const int bi = bh / HH, hi = bh % HH;
    {
        int r  = tid >> 2;
        int c0 = (tid & 3) * 16;
        float inv = 1.0f / ls[r];
        float* dst = AV + ((size_t)bi * SS + m0 + r) * DD + hi * DHD + c0;
        #pragma unroll
        for (int c = 0; c < 16; c += 4) {
            float4 v = *(float4*)&Ss[r * ATT_LDQ + c0 + c];
            v.x *= inv; v.y *= inv; v.z *= inv; v.w *= inv;
            *(float4*)&dst[c] = v;
        }
    }

    // rescale lower-triangle P by 1/rowsum
    {
        const int rl4 = zc0 >> 2;
        for (int i = tid; i < 128 * rl4; i += 512) {
            int r = i / rl4, c4 = (i - r * rl4) * 4;
            float inv = 1.0f / ls[r];
            float4 v = *(float4*)&Pb[(size_t)r * SS + c4];
            v.x *= inv; v.y *= inv; v.z *= inv; v.w *= inv;
            *(float4*)&Pb[(size_t)r * SS + c4] = v;
        }
    }
}

// ---------------- bias + exact GELU ----------------------------------------
__global__ void bias_gelu(float* __restrict__ F, const float* __restrict__ bias)
{
    const int idx4 = blockIdx.x * 256 + threadIdx.x;
    const size_t base = (size_t)idx4 * 4;
    float4 v = *(float4*)&F[base];
    const int col = (int)(base % DFF);
    float4 bb = *(const float4*)&bias[col];
    v.x += bb.x; v.y += bb.y; v.z += bb.z; v.w += bb.w;
    v.x = 0.5f * v.x * (1.0f + erff(v.x * 0.70710678118654752f));
    v.y = 0.5f * v.y * (1.0f + erff(v.y * 0.70710678118654752f));
    v.z = 0.5f * v.z * (1.0f + erff(v.z * 0.70710678118654752f));
    v.w = 0.5f * v.w * (1.0f + erff(v.w * 0.70710678118654752f));
    *(float4*)&F[base] = v;
}

// ---------------- fused residual add (+bias) + LayerNorm ------------------
__global__ void add_ln(const float* __restrict__ A, const float* __restrict__ Bv,
                       const float* __restrict__ bias,
                       const float* __restrict__ gamma, const float* __restrict__ beta,
                       float* __restrict__ out)
{
    const int row = blockIdx.x;
    const int tid = threadIdx.x;
    __shared__ float buf[DD];
    __shared__ float red[8];

    const float* a  = A  + (size_t)row * DD;
    const float* bp = Bv + (size_t)row * DD;

    float lsum = 0.f;
    #pragma unroll
    for (int i = 0; i < 3; i++) {
        int c = tid + i * 256;
        float v = a[c] + bp[c] + (bias ? bias[c] : 0.0f);
        buf[c] = v;
        lsum += v;
    }
    #pragma unroll
    for (int o = 16; o; o >>= 1) lsum += __shfl_xor_sync(0xffffffffu, lsum, o);
    if ((tid & 31) == 0) red[tid >> 5] = lsum;
    __syncthreads();
    float mu = (red[0]+red[1]+red[2]+red[3]+red[4]+red[5]+red[6]+red[7]) * (1.0f / DD);

    float lvar = 0.f;
    #pragma unroll
    for (int i = 0; i < 3; i++) {
        int c = tid + i * 256;
        float d = buf[c] - mu;
        lvar += d * d;
    }
    #pragma unroll
    for (int o = 16; o; o >>= 1) lvar += __shfl_xor_sync(0xffffffffu, lvar, o);
    __syncthreads();
    if ((tid & 31) == 0) red[tid >> 5] = lvar;
    __syncthreads();
    float var = (red[0]+red[1]+red[2]+red[3]+red[4]+red[5]+red[6]+red[7]) * (1.0f / DD);
    float inv = rsqrtf(var + 1e-5f);

    float* o = out + (size_t)row * DD;
    #pragma unroll
    for (int i = 0; i < 3; i++) {
        int c = tid + i * 256;
        o[c] = (buf[c] - mu) * inv * gamma[c] + beta[c];
    }
}

// ---------------------------------------------------------------------------
extern "C" void kernel_launch(void* const* d_in, const int* in_sizes, int n_in,
                              void* d_out, int out_size)
{
    const float* x   = (const float*)d_in[0];
    const float* Wq  = (const float*)d_in[2];
    const float* Wk  = (const float*)d_in[3];
    const float* Wv  = (const float*)d_in[4];
    const float* Wo  = (const float*)d_in[5];
    const float* bo  = (const float*)d_in[6];
    const float* g1  = (const float*)d_in[7];
    const float* b1  = (const float*)d_in[8];
    const float* W1  = (const float*)d_in[9];
    const float* bb1 = (const float*)d_in[10];
    const float* W2  = (const float*)d_in[11];
    const float* bb2 = (const float*)d_in[12];
    const float* g2  = (const float*)d_in[13];
    const float* b2  = (const float*)d_in[14];

    float* y = (float*)d_out;
    float* P = y + Y_ELEMS;

    float *qp, *kp, *vp, *avp, *aop, *hp, *f1p, *f2p;
    cudaGetSymbolAddress((void**)&qp,  g_q);
    cudaGetSymbolAddress((void**)&kp,  g_k);
    cudaGetSymbolAddress((void**)&vp,  g_v);
    cudaGetSymbolAddress((void**)&avp, g_av);
    cudaGetSymbolAddress((void**)&aop, g_ao);
    cudaGetSymbolAddress((void**)&hp,  g_h);
    cudaGetSymbolAddress((void**)&f1p, g_f1);
    cudaGetSymbolAddress((void**)&f2p, g_f2);

    cudaFuncSetAttribute(gemm_tc_nt, cudaFuncAttributeMaxDynamicSharedMemorySize,
                         GEMM_SMEM_BYTES);
    cudaFuncSetAttribute(qkv_gemm, cudaFuncAttributeMaxDynamicSharedMemorySize,
                         GEMM_SMEM_BYTES);
    static const size_t att_smem = (size_t)ATT_SMEM_FLOATS * sizeof(float);
    cudaFuncSetAttribute(attn_fused, cudaFuncAttributeMaxDynamicSharedMemorySize,
                         (int)att_smem);

    dim3 g768 (DD  / 128, MM / 128);
    dim3 g3072(DFF / 128, MM / 128);
    dim3 gqkv (DD  / 128, MM / 128, 3);

    // QKV projections: single merged launch, head-split outputs
    qkv_gemm<<<gqkv, 256, GEMM_SMEM_BYTES>>>(x, Wq, Wk, Wv, qp, kp, vp);

    // fused attention (cp.async pipelined)
    attn_fused<<<dim3(SS / 128, BB * HH), 512, att_smem>>>(qp, kp, vp, P, avp);

    // output projection (bias folded into add_ln)
    gemm_tc_nt<<<g768, 256, GEMM_SMEM_BYTES>>>(avp, Wo, aop, DD, DD);

    add_ln<<<MM, 256>>>(x, aop, bo, g1, b1, hp);

    gemm_tc_nt<<<g3072, 256, GEMM_SMEM_BYTES>>>(hp, W1, f1p, DFF, DD);
    bias_gelu<<<(int)((size_t)MM * DFF / 4 / 256), 256>>>(f1p, bb1);
    gemm_tc_nt<<<g768, 256, GEMM_SMEM_BYTES>>>(f1p, W2, f2p, DD, DFF);

    add_ln<<<MM, 256>>>(hp, f2p, bb2, g2, b2, y);
}

// round 8
// speedup vs baseline: 1.5369x; 1.0306x over previous
#include <cuda_runtime.h>
#include <cstdint>
#include <math.h>
#include <mma.h>

using namespace nvcuda;

// Problem constants
#define BB 2
#define SS 2048
#define HH 12
#define DHD 64
#define DD 768
#define DFF 3072
#define MM (BB*SS)
#define Y_ELEMS ((size_t)BB*SS*DD)

// ---------------- scratch (device globals) ---------------------------------
__device__ float g_q [BB*HH*SS*DHD];
__device__ float g_k [BB*HH*SS*DHD];
__device__ float g_v [BB*HH*SS*DHD];
__device__ float g_av[BB*SS*DD];
__device__ float g_ao[BB*SS*DD];
__device__ float g_h [BB*SS*DD];
__device__ float g_f1[BB*SS*DFF];
__device__ float g_f2[BB*SS*DD];

__device__ __forceinline__ void cp_async16(unsigned int dst, const void* src) {
    asm volatile("cp.async.cg.shared.global [%0], [%1], 16;\n" :: "r"(dst), "l"(src));
}
__device__ __forceinline__ void cp_commit() {
    asm volatile("cp.async.commit_group;\n");
}
__device__ __forceinline__ void cp_wait0() {
    asm volatile("cp.async.wait_group 0;\n");
}
__device__ __forceinline__ void cp_wait1() {
    asm volatile("cp.async.wait_group 1;\n");
}

// ============  tf32 NT GEMM, 3-stage cp.async pipeline  ====================
// Raw fp32 in smem; tf32 HMMA truncates mantissa in hardware (no cvt pass).
#define GLD 36
#define GBUF (128*GLD)
#define GSTG 3
#define GEMM_SMEM_BYTES (GSTG*2*GBUF*4)   // 110,592 B

// C[m,n] = sum_k A[m,k]*B[n,k]
template<int MODE>
__device__ __forceinline__ void gemm_body(const float* __restrict__ A,
                                          const float* __restrict__ B,
                                          float* __restrict__ C,
                                          int N, int K, int m0, int n0)
{
    extern __shared__ float gsm[];
    float* As = gsm;                    // [GSTG][128][36]
    float* Bs = gsm + GSTG*GBUF;        // [GSTG][128][36]

    const int tid  = threadIdx.x;
    const int warp = tid >> 5;
    const int wm   = warp & 1;
    const int wn   = warp >> 1;
    const int lr   = tid >> 3;          // 0..31
    const int lc4  = (tid & 7) * 4;     // 0..28

    const unsigned int as_s = (unsigned int)__cvta_generic_to_shared(As);
    const unsigned int bs_s = (unsigned int)__cvta_generic_to_shared(Bs);

    wmma::fragment<wmma::accumulator, 16, 16, 8, float> c[4][2];
    #pragma unroll
    for (int i = 0; i < 4; i++)
        #pragma unroll
        for (int j = 0; j < 2; j++)
            wmma::fill_fragment(c[i][j], 0.0f);

    const int T = K >> 5;

    // issue copy for k-tile t into stage t%GSTG
    auto issue = [&](int t) {
        const int k0 = t << 5;
        const unsigned int soff = (unsigned int)((t % GSTG) * GBUF * 4);
        #pragma unroll
        for (int i = 0; i < 4; i++) {
            int row = lr + i * 32;
            cp_async16(as_s + soff + (unsigned int)((row * GLD + lc4) * 4),
                       &A[(size_t)(m0 + row) * K + k0 + lc4]);
            cp_async16(bs_s + soff + (unsigned int)((row * GLD + lc4) * 4),
                       &B[(size_t)(n0 + row) * K + k0 + lc4]);
        }
        cp_commit();
    };

    issue(0);
    if (T > 1) issue(1);

    for (int t = 0; t < T; t++) {
        if (t + 1 < T) cp_wait1(); else cp_wait0();
        __syncthreads();
        if (t + 2 < T) issue(t + 2);

        const int cur = (t % GSTG) * GBUF;
        #pragma unroll
        for (int kk = 0; kk < 32; kk += 8) {
            wmma::fragment<wmma::matrix_a, 16, 16, 8, wmma::precision::tf32, wmma::row_major> a[4];
            wmma::fragment<wmma::matrix_b, 16, 16, 8, wmma::precision::tf32, wmma::col_major> b[2];
            #pragma unroll
            for (int i = 0; i < 4; i++)
                wmma::load_matrix_sync(a[i], &As[cur + (wm * 64 + i * 16) * GLD + kk], GLD);
            #pragma unroll
            for (int j = 0; j < 2; j++)
                wmma::load_matrix_sync(b[j], &Bs[cur + (wn * 32 + j * 16) * GLD + kk], GLD);
            #pragma unroll
            for (int i = 0; i < 4; i++)
                #pragma unroll
                for (int j = 0; j < 2; j++)
                    wmma::mma_sync(c[i][j], a[i], b[j], c[i][j]);
        }
        __syncthreads();
    }

    #pragma unroll
    for (int i = 0; i < 4; i++) {
        int m = m0 + wm * 64 + i * 16;
        #pragma unroll
        for (int j = 0; j < 2; j++) {
            int n = n0 + wn * 32 + j * 16;
            if (MODE == 3) {
                int bidx = m >> 11, s = m & 2047;
                int h = n >> 6, dh = n & 63;
                float* dst = C + (((size_t)(bidx * HH + h)) * SS + s) * DHD + dh;
                wmma::store_matrix_sync(dst, c[i][j], DHD, wmma::mem_row_major);
            } else {
                wmma::store_matrix_sync(C + (size_t)m * N + n, c[i][j], N, wmma::mem_row_major);
            }
        }
    }
}

__global__ void __launch_bounds__(256)
gemm_tc_nt(const float* __restrict__ A, const float* __restrict__ B,
           float* __restrict__ C, int N, int K)
{
    gemm_body<0>(A, B, C, N, K, blockIdx.y * 128, blockIdx.x * 128);
}

// merged QKV: grid.z selects (W, out) pair; head-split store
__global__ void __launch_bounds__(256)
qkv_gemm(const float* __restrict__ X,
         const float* __restrict__ Wq, const float* __restrict__ Wk,
         const float* __restrict__ Wv,
         float* __restrict__ Qo, float* __restrict__ Ko, float* __restrict__ Vo)
{
    const float* B = (blockIdx.z == 0) ? Wq : (blockIdx.z == 1) ? Wk : Wv;
    float*       C = (blockIdx.z == 0) ? Qo : (blockIdx.z == 1) ? Ko : Vo;
    gemm_body<3>(X, B, C, DD, DD, blockIdx.y * 128, blockIdx.x * 128);
}

// ==============  fused flash attention, cp.async pipelined  ================
// Raw fp32 everywhere; tf32 HMMA truncates in HW.
#define ATT_LDQ 68
#define QBUF (128*ATT_LDQ)
#define ATT_LDS 132
#define ATT_SMEM_FLOATS (4*QBUF + 128*ATT_LDS + 128)   // Q,K,V[2],S,ls

__global__ void __launch_bounds__(512, 1)
attn_fused(const float* __restrict__ Q, const float* __restrict__ K,
           const float* __restrict__ V, float* __restrict__ P,
           float* __restrict__ AV)
{
    extern __shared__ float sm[];
    float* Qs = sm;                 // [128][68]
    float* Ks = Qs + QBUF;          // [128][68]
    float* Vs = Ks + QBUF;          // [2][128][68]
    float* Ss = Vs + 2*QBUF;        // [128][132]
    float* ls = Ss + 128 * ATT_LDS; // [128]

    const int bh  = blockIdx.y;
    const int qt  = gridDim.x - 1 - blockIdx.x;
    const int m0  = qt * 128;
    const int tid = threadIdx.x;
    const int warp = tid >> 5;
    const int wm = warp & 3;
    const int wn = warp >> 2;

    const float* Qb = Q + ((size_t)bh * SS + m0) * DHD;
    const float* Kb = K + (size_t)bh * SS * DHD;
    const float* Vb = V + (size_t)bh * SS * DHD;
    float* Pb = P + ((size_t)bh * SS + m0) * SS;

    const int pr  = tid >> 4;
    const int pc4 = (tid & 15) * 4;
    const unsigned int ks_s = (unsigned int)__cvta_generic_to_shared(Ks);
    const unsigned int vs_s = (unsigned int)__cvta_generic_to_shared(Vs);

    // load Q tile, pre-scaled by 1/8
    for (int i = tid; i < 128 * 16; i += 512) {
        int r = i >> 4, c4 = (i & 15) * 4;
        float4 v = *(const float4*)&Qb[(size_t)r * DHD + c4];
        v.x *= 0.125f; v.y *= 0.125f; v.z *= 0.125f; v.w *= 0.125f;
        *(float4*)&Qs[r * ATT_LDQ + c4] = v;
    }
    if (tid < 128) ls[tid] = 0.0f;

    // issue copies for kt = 0
    #pragma unroll
    for (int u = 0; u < 4; u++) {
        int r = pr + u * 32;
        cp_async16(ks_s + (r * ATT_LDQ + pc4) * 4, &Kb[(size_t)r * DHD + pc4]);
        cp_async16(vs_s + (r * ATT_LDQ + pc4) * 4, &Vb[(size_t)r * DHD + pc4]);
    }
    cp_commit();

    wmma::fragment<wmma::accumulator, 16, 16, 8, float> co[2];
    #pragma unroll
    for (int i = 0; i < 2; i++) wmma::fill_fragment(co[i], 0.0f);

    for (int kt = 0; kt <= qt; kt++) {
        const int cur = (kt & 1) * QBUF;
        cp_wait0();
        __syncthreads();

        // S = Qs @ Ks^T  (warp tile 32x32)
        wmma::fragment<wmma::accumulator, 16, 16, 8, float> cs[2][2];
        #pragma unroll
        for (int i = 0; i < 2; i++)
            #pragma unroll
            for (int j = 0; j < 2; j++)
                wmma::fill_fragment(cs[i][j], 0.0f);

        #pragma unroll
        for (int kk = 0; kk < 64; kk += 8) {
            wmma::fragment<wmma::matrix_a, 16, 16, 8, wmma::precision::tf32, wmma::row_major> a[2];
            wmma::fragment<wmma::matrix_b, 16, 16, 8, wmma::precision::tf32, wmma::col_major> b[2];
            #pragma unroll
            for (int i = 0; i < 2; i++)
                wmma::load_matrix_sync(a[i], &Qs[(wm * 32 + i * 16) * ATT_LDQ + kk], ATT_LDQ);
            #pragma unroll
            for (int j = 0; j < 2; j++)
                wmma::load_matrix_sync(b[j], &Ks[(wn * 32 + j * 16) * ATT_LDQ + kk], ATT_LDQ);
            #pragma unroll
            for (int i = 0; i < 2; i++)
                #pragma unroll
                for (int j = 0; j < 2; j++)
                    wmma::mma_sync(cs[i][j], a[i], b[j], cs[i][j]);
        }
        #pragma unroll
        for (int i = 0; i < 2; i++)
            #pragma unroll
            for (int j = 0; j < 2; j++)
                wmma::store_matrix_sync(&Ss[(wm * 32 + i * 16) * ATT_LDS + wn * 32 + j * 16],
                                        cs[i][j], ATT_LDS, wmma::mem_row_major);
        __syncthreads();   // Ss visible; all warps done reading Ks

        // prefetch tiles for kt+1 (overlaps exp + O-MMA)
        if (kt < qt) {
            const int k1 = (kt + 1) * 128;
            const unsigned int vdst = vs_s + (((kt + 1) & 1) * QBUF) * 4;
            #pragma unroll
            for (int u = 0; u < 4; u++) {
                int r = pr + u * 32;
                cp_async16(ks_s + (r * ATT_LDQ + pc4) * 4, &Kb[(size_t)(k1 + r) * DHD + pc4]);
                cp_async16(vdst + (r * ATT_LDQ + pc4) * 4, &Vb[(size_t)(k1 + r) * DHD + pc4]);
            }
            cp_commit();
        }

        // exp + causal mask + rowsum; e -> P and Ss
        {
            const int k0 = kt * 128;
            int r  = tid >> 2;
            int c0 = (tid & 3) * 32;
            int grow = m0 + r;
            float partial = 0.0f;
            #pragma unroll
            for (int c = 0; c < 32; c += 4) {
                int gc = k0 + c0 + c;
                float4 v = *(float4*)&Ss[r * ATT_LDS + c0 + c];
                v.x = (gc + 0 <= grow) ? __expf(v.x) : 0.0f;
                v.y = (gc + 1 <= grow) ? __expf(v.y) : 0.0f;
                v.z = (gc + 2 <= grow) ? __expf(v.z) : 0.0f;
                v.w = (gc + 3 <= grow) ? __expf(v.w) : 0.0f;
                partial += v.x + v.y + v.z + v.w;
                *(float4*)&Pb[(size_t)r * SS + gc] = v;
                *(float4*)&Ss[r * ATT_LDS + c0 + c] = v;
            }
            atomicAdd(&ls[r], partial);
        }
        __syncthreads();

        // O += e @ V  (warp tile 32x16)
        #pragma unroll
        for (int kk = 0; kk < 128; kk += 8) {
            wmma::fragment<wmma::matrix_a, 16, 16, 8, wmma::precision::tf32, wmma::row_major> a[2];
            wmma::fragment<wmma::matrix_b, 16, 16, 8, wmma::precision::tf32, wmma::row_major> b;
            #pragma unroll
            for (int i = 0; i < 2; i++)
                wmma::load_matrix_sync(a[i], &Ss[(wm * 32 + i * 16) * ATT_LDS + kk], ATT_LDS);
            wmma::load_matrix_sync(b, &Vs[cur + kk * ATT_LDQ + wn * 16], ATT_LDQ);
            #pragma unroll
            for (int i = 0; i < 2; i++)
                wmma::mma_sync(co[i], a[i], b, co[i]);
        }
        __syncthreads();
    }

    // zero-fill fully masked P region
    const int zc0 = (qt + 1) * 128;
    if (zc0 < SS) {
        const int rl4 = (SS - zc0) >> 2;
        const float4 z4 = make_float4(0.f, 0.f, 0.f, 0.f);
        for (int i = tid; i < 128 * rl4; i += 512) {
            int r = i / rl4, c4 = (i - r * rl4) * 4;
            *(float4*)&Pb[(size_t)r * SS + zc0 + c4] = z4;
        }
    }

    // stage O to smem, normalize, write AV
    #pragma unroll
    for (int i = 0; i < 2; i++)
        wmma::store_matrix_sync(&Ss[(wm * 32 + i * 16) * ATT_LDQ + wn * 16],
                                co[i], ATT_LDQ, wmma::mem_row_major);
    __syncthreads();

    const int bi = bh / HH, hi = bh % HH;
    {
        int r  = tid >> 2;
        int c0 = (tid & 3) * 16;
        float inv = 1.0f / ls[r];
        float* dst = AV + ((size_t)bi * SS + m0 + r) * DD + hi * DHD + c0;
        #pragma unroll
        for (int c = 0; c < 16; c += 4) {
            float4 v = *(float4*)&Ss[r * ATT_LDQ + c0 + c];
            v.x *= inv; v.y *= inv; v.z *= inv; v.w *= inv;
            *(float4*)&dst[c] = v;
        }
    }

    // rescale lower-triangle P by 1/rowsum
    {
        const int rl4 = zc0 >> 2;
        for (int i = tid; i < 128 * rl4; i += 512) {
            int r = i / rl4, c4 = (i - r * rl4) * 4;
            float inv = 1.0f / ls[r];
            float4 v = *(float4*)&Pb[(size_t)r * SS + c4];
            v.x *= inv; v.y *= inv; v.z *= inv; v.w *= inv;
            *(float4*)&Pb[(size_t)r * SS + c4] = v;
        }
    }
}

// ---------------- bias + exact GELU ----------------------------------------
__global__ void bias_gelu(float* __restrict__ F, const float* __restrict__ bias)
{
    const int idx4 = blockIdx.x * 256 + threadIdx.x;
    const size_t base = (size_t)idx4 * 4;
    float4 v = *(float4*)&F[base];
    const int col = (int)(base % DFF);
    float4 bb = *(const float4*)&bias[col];
    v.x += bb.x; v.y += bb.y; v.z += bb.z; v.w += bb.w;
    v.x = 0.5f * v.x * (1.0f + erff(v.x * 0.70710678118654752f));
    v.y = 0.5f * v.y * (1.0f + erff(v.y * 0.70710678118654752f));
    v.z = 0.5f * v.z * (1.0f + erff(v.z * 0.70710678118654752f));
    v.w = 0.5f * v.w * (1.0f + erff(v.w * 0.70710678118654752f));
    *(float4*)&F[base] = v;
}

// ---------------- fused residual add (+bias) + LayerNorm ------------------
__global__ void add_ln(const float* __restrict__ A, const float* __restrict__ Bv,
                       const float* __restrict__ bias,
                       const float* __restrict__ gamma, const float* __restrict__ beta,
                       float* __restrict__ out)
{
    const int row = blockIdx.x;
    const int tid = threadIdx.x;
    __shared__ float buf[DD];
    __shared__ float red[8];

    const float* a  = A  + (size_t)row * DD;
    const float* bp = Bv + (size_t)row * DD;

    float lsum = 0.f;
    #pragma unroll
    for (int i = 0; i < 3; i++) {
        int c = tid + i * 256;
        float v = a[c] + bp[c] + (bias ? bias[c] : 0.0f);
        buf[c] = v;
        lsum += v;
    }
    #pragma unroll
    for (int o = 16; o; o >>= 1) lsum += __shfl_xor_sync(0xffffffffu, lsum, o);
    if ((tid & 31) == 0) red[tid >> 5] = lsum;
    __syncthreads();
    float mu = (red[0]+red[1]+red[2]+red[3]+red[4]+red[5]+red[6]+red[7]) * (1.0f / DD);

    float lvar = 0.f;
    #pragma unroll
    for (int i = 0; i < 3; i++) {
        int c = tid + i * 256;
        float d = buf[c] - mu;
        lvar += d * d;
    }
    #pragma unroll
    for (int o = 16; o; o >>= 1) lvar += __shfl_xor_sync(0xffffffffu, lvar, o);
    __syncthreads();
    if ((tid & 31) == 0) red[tid >> 5] = lvar;
    __syncthreads();
    float var = (red[0]+red[1]+red[2]+red[3]+red[4]+red[5]+red[6]+red[7]) * (1.0f / DD);
    float inv = rsqrtf(var + 1e-5f);

    float* o = out + (size_t)row * DD;
    #pragma unroll
    for (int i = 0; i < 3; i++) {
        int c = tid + i * 256;
        o[c] = (buf[c] - mu) * inv * gamma[c] + beta[c];
    }
}

// ---------------------------------------------------------------------------
extern "C" void kernel_launch(void* const* d_in, const int* in_sizes, int n_in,
                              void* d_out, int out_size)
{
    const float* x   = (const float*)d_in[0];
    const float* Wq  = (const float*)d_in[2];
    const float* Wk  = (const float*)d_in[3];
    const float* Wv  = (const float*)d_in[4];
    const float* Wo  = (const float*)d_in[5];
    const float* bo  = (const float*)d_in[6];
    const float* g1  = (const float*)d_in[7];
    const float* b1  = (const float*)d_in[8];
    const float* W1  = (const float*)d_in[9];
    const float* bb1 = (const float*)d_in[10];
    const float* W2  = (const float*)d_in[11];
    const float* bb2 = (const float*)d_in[12];
    const float* g2  = (const float*)d_in[13];
    const float* b2  = (const float*)d_in[14];

    float* y = (float*)d_out;
    float* P = y + Y_ELEMS;

    float *qp, *kp, *vp, *avp, *aop, *hp, *f1p, *f2p;
    cudaGetSymbolAddress((void**)&qp,  g_q);
    cudaGetSymbolAddress((void**)&kp,  g_k);
    cudaGetSymbolAddress((void**)&vp,  g_v);
    cudaGetSymbolAddress((void**)&avp, g_av);
    cudaGetSymbolAddress((void**)&aop, g_ao);
    cudaGetSymbolAddress((void**)&hp,  g_h);
    cudaGetSymbolAddress((void**)&f1p, g_f1);
    cudaGetSymbolAddress((void**)&f2p, g_f2);

    cudaFuncSetAttribute(gemm_tc_nt, cudaFuncAttributeMaxDynamicSharedMemorySize,
                         GEMM_SMEM_BYTES);
    cudaFuncSetAttribute(qkv_gemm, cudaFuncAttributeMaxDynamicSharedMemorySize,
                         GEMM_SMEM_BYTES);
    static const size_t att_smem = (size_t)ATT_SMEM_FLOATS * sizeof(float);
    cudaFuncSetAttribute(attn_fused, cudaFuncAttributeMaxDynamicSharedMemorySize,
                         (int)att_smem);

    dim3 g768 (DD  / 128, MM / 128);
    dim3 g3072(DFF / 128, MM / 128);
    dim3 gqkv (DD  / 128, MM / 128, 3);

    // QKV projections: single merged launch, head-split outputs
    qkv_gemm<<<gqkv, 256, GEMM_SMEM_BYTES>>>(x, Wq, Wk, Wv, qp, kp, vp);

    // fused attention (cp.async pipelined)
    attn_fused<<<dim3(SS / 128, BB * HH), 512, att_smem>>>(qp, kp, vp, P, avp);

    // output projection (bias folded into add_ln)
    gemm_tc_nt<<<g768, 256, GEMM_SMEM_BYTES>>>(avp, Wo, aop, DD, DD);

    add_ln<<<MM, 256>>>(x, aop, bo, g1, b1, hp);

    gemm_tc_nt<<<g3072, 256, GEMM_SMEM_BYTES>>>(hp, W1, f1p, DFF, DD);
    bias_gelu<<<(int)((size_t)MM * DFF / 4 / 256), 256>>>(f1p, bb1);
    gemm_tc_nt<<<g768, 256, GEMM_SMEM_BYTES>>>(f1p, W2, f2p, DD, DFF);

    add_ln<<<MM, 256>>>(hp, f2p, bb2, g2, b2, y);
}